// round 14
// baseline (speedup 1.0000x reference)
#include <cuda_runtime.h>
#include <cuda_fp16.h>

// ---------------------------------------------------------------------------
// GCN forward, round 13 (base = round 12 @324.4us + ONE change):
//   All activations now flow in fp16: spmm stores fp16 (BN stats still exact
//   fp32, computed pre-rounding), GEMM2/head read fp16 A via a second loader.
//   Cuts ~90MB of L2 traffic per call.
// ---------------------------------------------------------------------------

#define NMAXN 50000
#define EMAX  800000
#define FDIM  256
#define EPSV  1e-5f
#define RPW   10          // rows per warp in spmm_csr

__device__ __half g_hbuf[(size_t)NMAXN * FDIM];    // gemm output (fp16)
__device__ __half g_hbuf2[(size_t)NMAXN * FDIM];   // spmm output (fp16)
__device__ float  g_sum1[FDIM];
__device__ float  g_sumsq1[FDIM];
__device__ float  g_sum2[FDIM];
__device__ float  g_sumsq2[FDIM];

__device__ int   g_cnt[NMAXN];       // histogram (zero before & after each call)
__device__ int   g_cursor[NMAXN];
__device__ int   g_ptr[NMAXN + 1];
__device__ int   g_blk[64];
__device__ int   g_ccol[EMAX];
__device__ float g_cval[EMAX];

__device__ __forceinline__ unsigned f2tf(float f) {
    unsigned u;
    asm("cvt.rna.tf32.f32 %0, %1;" : "=r"(u) : "f"(f));
    return u;
}

// ---------------------------------------------------------------------------
// CSR build
// ---------------------------------------------------------------------------
__global__ void hist_kernel(const int* __restrict__ er, int E) {
    int e = blockIdx.x * blockDim.x + threadIdx.x;
    if (e < E) atomicAdd(&g_cnt[er[e]], 1);
}

__global__ __launch_bounds__(1024) void scan1_kernel(int n) {
    __shared__ int wsum[32];
    int tid = threadIdx.x;
    int i = blockIdx.x * 1024 + tid;
    int lane = tid & 31, wid = tid >> 5;
    int v = 0;
    if (i < n) {
        v = g_cnt[i];
        g_cnt[i] = 0;          // restore zero-invariant
    }
    int x = v;
    #pragma unroll
    for (int d = 1; d < 32; d <<= 1) {
        int t = __shfl_up_sync(0xffffffffu, x, d);
        if (lane >= d) x += t;
    }
    if (lane == 31) wsum[wid] = x;
    __syncthreads();
    if (wid == 0) {
        int y = wsum[lane];
        #pragma unroll
        for (int d = 1; d < 32; d <<= 1) {
            int t = __shfl_up_sync(0xffffffffu, y, d);
            if (lane >= d) y += t;
        }
        wsum[lane] = y;
    }
    __syncthreads();
    int incl = x + (wid > 0 ? wsum[wid - 1] : 0);
    if (i < n) g_ptr[i] = incl - v;
    if (tid == 1023) g_blk[blockIdx.x] = incl;
}

__global__ __launch_bounds__(1024) void scan3_kernel(int n, int E) {
    __shared__ int soff[2];
    int tid = threadIdx.x;
    if (tid < 64) {
        int v = (tid < blockIdx.x) ? g_blk[tid] : 0;
        #pragma unroll
        for (int d = 16; d > 0; d >>= 1)
            v += __shfl_down_sync(0xffffffffu, v, d);
        if ((tid & 31) == 0) soff[tid >> 5] = v;
    }
    __syncthreads();
    int off = soff[0] + soff[1];
    int i = blockIdx.x * 1024 + tid;
    if (i < n) {
        int p = g_ptr[i] + off;
        g_ptr[i] = p;
        g_cursor[i] = p;
    }
    if (i == 0) g_ptr[n] = E;
    if (i < FDIM) {
        g_sum1[i] = 0.f; g_sumsq1[i] = 0.f;
        g_sum2[i] = 0.f; g_sumsq2[i] = 0.f;
    }
}

__global__ void scatter_kernel(const int* __restrict__ er, const int* __restrict__ ec,
                               const float* __restrict__ ev, int E) {
    int e = blockIdx.x * blockDim.x + threadIdx.x;
    if (e >= E) return;
    int pos = atomicAdd(&g_cursor[er[e]], 1);
    g_ccol[pos] = ec[e];
    g_cval[pos] = ev[e];
}

// ---------------------------------------------------------------------------
// CSR SpMM (fp16 gather -> fp32 accum -> fp16 output) with fused BN stats.
// Stats accumulated from exact fp32 values BEFORE the fp16 store.
// Lane owns cols lane*8..lane*8+7 (one uint4 of 8 halves per row).
// ---------------------------------------------------------------------------
__global__ __launch_bounds__(256) void spmm_csr(
    const uint4* __restrict__ x, uint4* __restrict__ out16,
    float* __restrict__ sumbuf, float* __restrict__ sqbuf, int N)
{
    __shared__ __align__(16) float4 sm_s[8][64];
    __shared__ __align__(16) float4 sm_q[8][64];

    int lane = threadIdx.x & 31;
    int w = threadIdx.x >> 5;
    int r0 = (blockIdx.x * 8 + w) * RPW;

    float s[8] = {}, q[8] = {};

    int rend = min(r0 + RPW, N);
    for (int r = r0; r < rend; r++) {
        int e = __ldg(&g_ptr[r]);
        int end = __ldg(&g_ptr[r + 1]);
        float a[8] = {};
        for (; e + 1 < end; e += 2) {
            int   c0 = __ldg(&g_ccol[e]),  c1 = __ldg(&g_ccol[e + 1]);
            float w0 = __ldg(&g_cval[e]),  w1 = __ldg(&g_cval[e + 1]);
            uint4 u = __ldg(x + (size_t)c0 * 32 + lane);
            uint4 v = __ldg(x + (size_t)c1 * 32 + lane);
            const unsigned* up = &u.x;
            const unsigned* vp = &v.x;
            #pragma unroll
            for (int j = 0; j < 4; j++) {
                float2 fu = __half22float2(*reinterpret_cast<const __half2*>(&up[j]));
                float2 fv = __half22float2(*reinterpret_cast<const __half2*>(&vp[j]));
                a[j * 2 + 0] = fmaf(w0, fu.x, fmaf(w1, fv.x, a[j * 2 + 0]));
                a[j * 2 + 1] = fmaf(w0, fu.y, fmaf(w1, fv.y, a[j * 2 + 1]));
            }
        }
        if (e < end) {
            int   c0 = __ldg(&g_ccol[e]);
            float w0 = __ldg(&g_cval[e]);
            uint4 u = __ldg(x + (size_t)c0 * 32 + lane);
            const unsigned* up = &u.x;
            #pragma unroll
            for (int j = 0; j < 4; j++) {
                float2 fu = __half22float2(*reinterpret_cast<const __half2*>(&up[j]));
                a[j * 2 + 0] = fmaf(w0, fu.x, a[j * 2 + 0]);
                a[j * 2 + 1] = fmaf(w0, fu.y, a[j * 2 + 1]);
            }
        }
        // stats from exact fp32 values
        #pragma unroll
        for (int j = 0; j < 8; j++) {
            s[j] += a[j];
            q[j] = fmaf(a[j], a[j], q[j]);
        }
        // fp16 store (one uint4 = 8 halves)
        __half2 h0 = __floats2half2_rn(a[0], a[1]);
        __half2 h1 = __floats2half2_rn(a[2], a[3]);
        __half2 h2 = __floats2half2_rn(a[4], a[5]);
        __half2 h3 = __floats2half2_rn(a[6], a[7]);
        uint4 o;
        o.x = *reinterpret_cast<unsigned*>(&h0);
        o.y = *reinterpret_cast<unsigned*>(&h1);
        o.z = *reinterpret_cast<unsigned*>(&h2);
        o.w = *reinterpret_cast<unsigned*>(&h3);
        out16[(size_t)r * 32 + lane] = o;
    }

    sm_s[w][lane * 2]     = make_float4(s[0], s[1], s[2], s[3]);
    sm_s[w][lane * 2 + 1] = make_float4(s[4], s[5], s[6], s[7]);
    sm_q[w][lane * 2]     = make_float4(q[0], q[1], q[2], q[3]);
    sm_q[w][lane * 2 + 1] = make_float4(q[4], q[5], q[6], q[7]);
    __syncthreads();

    int t = threadIdx.x;
    if (t < 64) {
        float4 acc = sm_s[0][t];
        #pragma unroll
        for (int ww = 1; ww < 8; ww++) {
            float4 v = sm_s[ww][t];
            acc.x += v.x; acc.y += v.y; acc.z += v.z; acc.w += v.w;
        }
        int c = t * 4;
        atomicAdd(&sumbuf[c + 0], acc.x); atomicAdd(&sumbuf[c + 1], acc.y);
        atomicAdd(&sumbuf[c + 2], acc.z); atomicAdd(&sumbuf[c + 3], acc.w);
    } else if (t < 128) {
        int sl = t - 64;
        float4 acc = sm_q[0][sl];
        #pragma unroll
        for (int ww = 1; ww < 8; ww++) {
            float4 v = sm_q[ww][sl];
            acc.x += v.x; acc.y += v.y; acc.z += v.z; acc.w += v.w;
        }
        int c = sl * 4;
        atomicAdd(&sqbuf[c + 0], acc.x); atomicAdd(&sqbuf[c + 1], acc.y);
        atomicAdd(&sqbuf[c + 2], acc.z); atomicAdd(&sqbuf[c + 3], acc.w);
    }
}

// ---------------------------------------------------------------------------
// Software-pipelined tf32 GEMM: C = op(A) @ B (+ bias).
// A source: fp32 (A) when Ah==null, else fp16 (Ah). bn_gamma!=null enables
// inline BN finalize into smem + relu(x*scale+shift) on the A-path.
// Output: fp16 (Ch != null) else fp32 (C).
// ---------------------------------------------------------------------------
__global__ __launch_bounds__(256) void gemm_tf32(
    const float* __restrict__ A, const __half* __restrict__ Ah,
    const float* __restrict__ B,
    const float* __restrict__ bias, const int* __restrict__ gather,
    const float* __restrict__ bn_sum, const float* __restrict__ bn_sq,
    const float* __restrict__ bn_gamma, const float* __restrict__ bn_beta,
    float invN, float* __restrict__ C, __half* __restrict__ Ch,
    int M, int Ncols, int K)
{
    __shared__ __align__(16) float As[128 * 36];
    __shared__ __align__(16) float Bs[32 * 72];
    __shared__ float s_scale[FDIM];
    __shared__ float s_shift[FDIM];

    int tid = threadIdx.x;
    int lane = tid & 31, w = tid >> 5;
    int wm = w >> 1, wn = w & 1;
    int g = lane >> 2, tg = lane & 3;
    int row0 = blockIdx.y * 128, col0 = blockIdx.x * 64;

    if (bn_gamma) {
        float m = bn_sum[tid] * invN;
        float var = bn_sq[tid] * invN - m * m;
        float sc = rsqrtf(var + EPSV) * bn_gamma[tid];
        s_scale[tid] = sc;
        s_shift[tid] = bn_beta[tid] - m * sc;
    }
    __syncthreads();

    float acc[2][4][4];
    #pragma unroll
    for (int mi = 0; mi < 2; mi++)
        #pragma unroll
        for (int ni = 0; ni < 4; ni++)
            #pragma unroll
            for (int j = 0; j < 4; j++) acc[mi][ni][j] = 0.f;

    // A source rows. fp32 path: 4 slots (idx>>3). fp16 path: 2 slots (idx>>2).
    int asrc[4];
    if (Ah) {
        #pragma unroll
        for (int p = 0; p < 2; p++) {
            int idx = tid + p * 256;
            int grow = row0 + (idx >> 2);
            int sr = grow < M ? grow : M - 1;
            if (gather) sr = __ldg(gather + sr);
            asrc[p] = sr;
        }
    } else {
        #pragma unroll
        for (int p = 0; p < 4; p++) {
            int idx = tid + p * 256;
            int grow = row0 + (idx >> 3);
            int sr = grow < M ? grow : M - 1;
            if (gather) sr = __ldg(gather + sr);
            asrc[p] = sr;
        }
    }

    float4 ra[4];
    uint4  ra16[2];
    float4 rb[2];
    if (Ah) {
        #pragma unroll
        for (int p = 0; p < 2; p++) {
            int idx = tid + p * 256;
            ra16[p] = *reinterpret_cast<const uint4*>(
                Ah + (size_t)asrc[p] * K + (idx & 3) * 8);
        }
    } else {
        #pragma unroll
        for (int p = 0; p < 4; p++) {
            int idx = tid + p * 256;
            ra[p] = *reinterpret_cast<const float4*>(
                A + (size_t)asrc[p] * K + (idx & 7) * 4);
        }
    }
    #pragma unroll
    for (int p = 0; p < 2; p++) {
        int idx = tid + p * 256;
        rb[p] = *reinterpret_cast<const float4*>(
            B + (size_t)(idx >> 4) * Ncols + col0 + (idx & 15) * 4);
    }

    for (int kt = 0; kt < K; kt += 32) {
        if (Ah) {
            #pragma unroll
            for (int p = 0; p < 2; p++) {
                int idx = tid + p * 256;
                int row = idx >> 2, c8 = idx & 3;
                int cb = kt + c8 * 8;
                const unsigned* up = &ra16[p].x;
                float vv[8];
                #pragma unroll
                for (int j = 0; j < 4; j++) {
                    float2 f = __half22float2(*reinterpret_cast<const __half2*>(&up[j]));
                    vv[j * 2 + 0] = f.x;
                    vv[j * 2 + 1] = f.y;
                }
                if (bn_gamma) {
                    #pragma unroll
                    for (int j = 0; j < 8; j++)
                        vv[j] = fmaxf(fmaf(vv[j], s_scale[cb + j], s_shift[cb + j]), 0.f);
                }
                float4 o0, o1;
                o0.x = __uint_as_float(f2tf(vv[0]));
                o0.y = __uint_as_float(f2tf(vv[1]));
                o0.z = __uint_as_float(f2tf(vv[2]));
                o0.w = __uint_as_float(f2tf(vv[3]));
                o1.x = __uint_as_float(f2tf(vv[4]));
                o1.y = __uint_as_float(f2tf(vv[5]));
                o1.z = __uint_as_float(f2tf(vv[6]));
                o1.w = __uint_as_float(f2tf(vv[7]));
                *reinterpret_cast<float4*>(As + row * 36 + c8 * 8)     = o0;
                *reinterpret_cast<float4*>(As + row * 36 + c8 * 8 + 4) = o1;
            }
        } else {
            #pragma unroll
            for (int p = 0; p < 4; p++) {
                int idx = tid + p * 256;
                int row = idx >> 3, c4 = idx & 7;
                float4 v = ra[p];
                float4 o;
                o.x = __uint_as_float(f2tf(v.x));
                o.y = __uint_as_float(f2tf(v.y));
                o.z = __uint_as_float(f2tf(v.z));
                o.w = __uint_as_float(f2tf(v.w));
                *reinterpret_cast<float4*>(As + row * 36 + c4 * 4) = o;
            }
        }
        #pragma unroll
        for (int p = 0; p < 2; p++) {
            int idx = tid + p * 256;
            int row = idx >> 4, c4 = idx & 15;
            float4 v = rb[p];
            float4 o;
            o.x = __uint_as_float(f2tf(v.x));
            o.y = __uint_as_float(f2tf(v.y));
            o.z = __uint_as_float(f2tf(v.z));
            o.w = __uint_as_float(f2tf(v.w));
            *reinterpret_cast<float4*>(Bs + row * 72 + c4 * 4) = o;
        }
        __syncthreads();

        int ktn = kt + 32;
        if (ktn < K) {
            if (Ah) {
                #pragma unroll
                for (int p = 0; p < 2; p++) {
                    int idx = tid + p * 256;
                    ra16[p] = *reinterpret_cast<const uint4*>(
                        Ah + (size_t)asrc[p] * K + ktn + (idx & 3) * 8);
                }
            } else {
                #pragma unroll
                for (int p = 0; p < 4; p++) {
                    int idx = tid + p * 256;
                    ra[p] = *reinterpret_cast<const float4*>(
                        A + (size_t)asrc[p] * K + ktn + (idx & 7) * 4);
                }
            }
            #pragma unroll
            for (int p = 0; p < 2; p++) {
                int idx = tid + p * 256;
                rb[p] = *reinterpret_cast<const float4*>(
                    B + (size_t)(ktn + (idx >> 4)) * Ncols + col0 + (idx & 15) * 4);
            }
        }

        #pragma unroll
        for (int kk = 0; kk < 4; kk++) {
            unsigned a[2][4], b[4][2];
            #pragma unroll
            for (int mi = 0; mi < 2; mi++) {
                int rb_ = wm * 32 + mi * 16;
                int kc = kk * 8 + tg;
                a[mi][0] = __float_as_uint(As[(rb_ + g)     * 36 + kc]);
                a[mi][1] = __float_as_uint(As[(rb_ + g + 8) * 36 + kc]);
                a[mi][2] = __float_as_uint(As[(rb_ + g)     * 36 + kc + 4]);
                a[mi][3] = __float_as_uint(As[(rb_ + g + 8) * 36 + kc + 4]);
            }
            #pragma unroll
            for (int ni = 0; ni < 4; ni++) {
                int col = wn * 32 + ni * 8 + g;
                b[ni][0] = __float_as_uint(Bs[(kk * 8 + tg)     * 72 + col]);
                b[ni][1] = __float_as_uint(Bs[(kk * 8 + tg + 4) * 72 + col]);
            }
            #pragma unroll
            for (int mi = 0; mi < 2; mi++)
                #pragma unroll
                for (int ni = 0; ni < 4; ni++)
                    asm volatile(
                        "mma.sync.aligned.m16n8k8.row.col.f32.tf32.tf32.f32 "
                        "{%0,%1,%2,%3}, {%4,%5,%6,%7}, {%8,%9}, {%0,%1,%2,%3};"
                        : "+f"(acc[mi][ni][0]), "+f"(acc[mi][ni][1]),
                          "+f"(acc[mi][ni][2]), "+f"(acc[mi][ni][3])
                        : "r"(a[mi][0]), "r"(a[mi][1]), "r"(a[mi][2]), "r"(a[mi][3]),
                          "r"(b[ni][0]), "r"(b[ni][1]));
        }
        __syncthreads();
    }

    #pragma unroll
    for (int mi = 0; mi < 2; mi++) {
        int r = row0 + wm * 32 + mi * 16 + g;
        #pragma unroll
        for (int ni = 0; ni < 4; ni++) {
            int c = col0 + wn * 32 + ni * 8 + tg * 2;
            float bx = bias ? __ldg(bias + c) : 0.f;
            float by = bias ? __ldg(bias + c + 1) : 0.f;
            float v0 = acc[mi][ni][0] + bx, v1 = acc[mi][ni][1] + by;
            float v2 = acc[mi][ni][2] + bx, v3 = acc[mi][ni][3] + by;
            if (Ch) {
                if (r < M)
                    *reinterpret_cast<__half2*>(Ch + (size_t)r * Ncols + c) =
                        __floats2half2_rn(v0, v1);
                if (r + 8 < M)
                    *reinterpret_cast<__half2*>(Ch + (size_t)(r + 8) * Ncols + c) =
                        __floats2half2_rn(v2, v3);
            } else {
                if (r < M)
                    *reinterpret_cast<float2*>(C + (size_t)r * Ncols + c) =
                        make_float2(v0, v1);
                if (r + 8 < M)
                    *reinterpret_cast<float2*>(C + (size_t)(r + 8) * Ncols + c) =
                        make_float2(v2, v3);
            }
        }
    }
}

// ---------------------------------------------------------------------------
// Launch sequence (single stream, graph-capturable: kernels only, 9 launches).
// ---------------------------------------------------------------------------
extern "C" void kernel_launch(void* const* d_in, const int* in_sizes, int n_in,
                              void* d_out, int out_size) {
    const float* features  = (const float*)d_in[0];
    const float* edge_vals = (const float*)d_in[1];
    const float* W1  = (const float*)d_in[2];
    const float* db1 = (const float*)d_in[3];
    // d_in[4] = b1  : cancels in BatchNorm
    const float* g1  = (const float*)d_in[5];
    const float* be1 = (const float*)d_in[6];
    const float* W2  = (const float*)d_in[7];
    // d_in[8] = b2  : cancels in BatchNorm
    const float* g2  = (const float*)d_in[9];
    const float* be2 = (const float*)d_in[10];
    const float* Wf  = (const float*)d_in[11];
    const float* bf  = (const float*)d_in[12];
    const int* erows = (const int*)d_in[13];
    const int* ecols = (const int*)d_in[14];
    const int* idx   = (const int*)d_in[15];
    float* out = (float*)d_out;

    int N = in_sizes[0] / FDIM;   // 50000
    int E = in_sizes[1];          // 800000
    int M = in_sizes[15];         // 25000
    float invN = 1.0f / (float)N;

    float *su1, *sq1, *su2, *sq2;
    __half *hb, *hb2;
    cudaGetSymbolAddress((void**)&hb, g_hbuf);
    cudaGetSymbolAddress((void**)&hb2, g_hbuf2);
    cudaGetSymbolAddress((void**)&su1, g_sum1);
    cudaGetSymbolAddress((void**)&sq1, g_sumsq1);
    cudaGetSymbolAddress((void**)&su2, g_sum2);
    cudaGetSymbolAddress((void**)&sq2, g_sumsq2);

    int eblocks = (E + 255) / 256;
    int nb = (N + 1023) / 1024;
    dim3 ggrid(FDIM / 64, (N + 127) / 128);
    int spmm_blocks = (N + 8 * RPW - 1) / (8 * RPW);

    // CSR build
    hist_kernel<<<eblocks, 256>>>(erows, E);
    scan1_kernel<<<nb, 1024>>>(N);
    scan3_kernel<<<nb, 1024>>>(N, E);
    scatter_kernel<<<eblocks, 256>>>(erows, ecols, edge_vals, E);

    // layer 1: gemm(features fp32) -> fp16 hb; spmm hb -> fp16 hb2 + stats1
    gemm_tf32<<<ggrid, 256>>>(features, nullptr, W1, db1, nullptr,
                              nullptr, nullptr, nullptr, nullptr, 0.f,
                              nullptr, hb, N, FDIM, FDIM);
    spmm_csr<<<spmm_blocks, 256>>>((const uint4*)hb, (uint4*)hb2, su1, sq1, N);

    // layer 2: gemm(A=fp16 hb2, BN1 inline) -> fp16 hb; spmm -> hb2 + stats2
    gemm_tf32<<<ggrid, 256>>>(nullptr, hb2, W2, nullptr, nullptr,
                              su1, sq1, g1, be1, invN,
                              nullptr, hb, N, FDIM, FDIM);
    spmm_csr<<<spmm_blocks, 256>>>((const uint4*)hb, (uint4*)hb2, su2, sq2, N);

    // head: gemm(A=fp16 hb2, BN2 inline, gather) -> fp32 out
    gemm_tf32<<<dim3(128 / 64, (M + 127) / 128), 256>>>(
        nullptr, hb2, Wf, bf, idx,
        su2, sq2, g2, be2, invN,
        out, nullptr, M, 128, FDIM);
}